// round 4
// baseline (speedup 1.0000x reference)
#include <cuda_runtime.h>
#include <cstdint>
#include <cstddef>

#define BB 64
#define VV 2048
#define HH 128
#define NNODE (BB*VV)      /* 131072 */
#define EE 1048576
#define CFD 47
#define EPSB 1e-5f

// ---------------- device scratch (allocation-free rule) ----------------
__device__ __align__(16) float g_Y1e[(size_t)EE*HH];      // 512MB  X@w1+b1 (pre-BN)
__device__ __align__(16) float g_H2[(size_t)EE*2*HH];     // 1GB    silu(BN1)@w2+b2 (pre-BN)
__device__ __align__(16) float g_h[(size_t)NNODE*HH];     // 64MB
__device__ __align__(16) float g_hprop[(size_t)NNODE*HH];
__device__ __align__(16) float g_y1[(size_t)NNODE*HH];
__device__ __align__(16) float g_y2[(size_t)NNODE*HH];
__device__ __align__(16) float g_hspec[(size_t)BB*HH*HH]; // 4MB
__device__ float g_stsum[2*HH];
__device__ float g_stsq[2*HH];
__device__ float g_affA[2*HH];
__device__ float g_affC[2*HH];
__device__ float g_outacc[BB];

__device__ __forceinline__ float siluf(float x){ return x/(1.f+__expf(-x)); }

// ---------------- zero kernels ----------------
__global__ void k_zero_h(){
    size_t i=(size_t)blockIdx.x*blockDim.x+threadIdx.x;
    ((float4*)g_h)[i]=make_float4(0.f,0.f,0.f,0.f);
    if(blockIdx.x==0&&threadIdx.x<BB) g_outacc[threadIdx.x]=0.f;
}
__global__ void k_zero_spec(){
    size_t i=(size_t)blockIdx.x*blockDim.x+threadIdx.x;
    ((float4*)g_hspec)[i]=make_float4(0.f,0.f,0.f,0.f);
}
__global__ void k_zero_st(){
    int t=threadIdx.x;
    if(t<2*HH){ g_stsum[t]=0.f; g_stsq[t]=0.f; }
}

// ---------------- GEMM1: Y1 = X@w1 + b1 (K=47), with column stats ----------------
__global__ __launch_bounds__(256) void k_gemm1(const float* __restrict__ X,
                                               const float* __restrict__ w1,
                                               const float* __restrict__ b1){
    __shared__ float ws[CFD*HH];    // [k][j], also reused as 16x128 stats scratch
    __shared__ float xs[128*48];    // padded rows
    int t=threadIdx.x, ty=t>>4, tx=t&15;
    size_t m0=(size_t)blockIdx.x*128;
    for(int i=t;i<CFD*HH;i+=256) ws[i]=w1[i];
    const float* src=X+m0*CFD;
    for(int i=t;i<128*CFD;i+=256) xs[(i/CFD)*48+(i%CFD)]=src[i];
    __syncthreads();
    float acc[8][8]={};
    for(int k=0;k<CFD;k++){
        float4 c0=*(const float4*)&ws[k*HH+tx*8];
        float4 c1=*(const float4*)&ws[k*HH+tx*8+4];
        float bv[8]={c0.x,c0.y,c0.z,c0.w,c1.x,c1.y,c1.z,c1.w};
        #pragma unroll
        for(int ri=0;ri<8;ri++){
            float a=xs[(ty*8+ri)*48+k];
            #pragma unroll
            for(int ci=0;ci<8;ci++) acc[ri][ci]+=a*bv[ci];
        }
    }
    float bb[8];
    #pragma unroll
    for(int ci=0;ci<8;ci++) bb[ci]=b1[tx*8+ci];
    float ls[8]={}, lq[8]={};
    #pragma unroll
    for(int ri=0;ri<8;ri++){
        float v[8];
        #pragma unroll
        for(int ci=0;ci<8;ci++){ v[ci]=acc[ri][ci]+bb[ci]; ls[ci]+=v[ci]; lq[ci]+=v[ci]*v[ci]; }
        size_t row=m0+ty*8+ri;
        *(float4*)&g_Y1e[row*HH+tx*8]  =make_float4(v[0],v[1],v[2],v[3]);
        *(float4*)&g_Y1e[row*HH+tx*8+4]=make_float4(v[4],v[5],v[6],v[7]);
    }
    __syncthreads();
    #pragma unroll
    for(int ci=0;ci<8;ci++) ws[ty*128+tx*8+ci]=ls[ci];
    __syncthreads();
    if(t<128){ float s=0.f; for(int q=0;q<16;q++) s+=ws[q*128+t]; atomicAdd(&g_stsum[t],s); }
    __syncthreads();
    #pragma unroll
    for(int ci=0;ci<8;ci++) ws[ty*128+tx*8+ci]=lq[ci];
    __syncthreads();
    if(t<128){ float s=0.f; for(int q=0;q<16;q++) s+=ws[q*128+t]; atomicAdd(&g_stsq[t],s); }
}

// ---------------- fold stats -> affine ----------------
__global__ void k_fold(int ncols, float invn,
                       const float* __restrict__ g, const float* __restrict__ be){
    int j=threadIdx.x;
    if(j<ncols){
        float m=g_stsum[j]*invn;
        float var=g_stsq[j]*invn-m*m;
        float A=g[j]*rsqrtf(var+EPSB);
        g_affA[j]=A;
        g_affC[j]=be[j]-A*m;
    }
}

// ---------------- generic 128x128 tiled GEMM ----------------
// mode 0: plain A           mode 1: A = concat(g_h, g_hprop), Kdim=256
// mode 2: A elem -> silu(affA*a+affC)
// mode 3: A = evecs from eigs (per-batch), B = g_hspec per-batch
// asel: 0=g_Y1e 1=g_h 2=g_y1 ; csel: 0=g_H2 1=g_hprop 2=g_y1 3=g_y2
__global__ __launch_bounds__(256) void k_mm(int mode, int asel, int csel,
        const float* __restrict__ eigs,
        const float* __restrict__ Bw, int ldb,
        const float* __restrict__ bias,
        int ldc, int Kdim, int do_stats)
{
    __shared__ float As[16*128];
    __shared__ float Bs[16*128];
    const float* A=(asel==0)?g_Y1e:(asel==1)?g_h:g_y1;
    float* Cout=(csel==0)?g_H2:(csel==1)?g_hprop:(csel==2)?g_y1:g_y2;
    int t=threadIdx.x, ty=t>>4, tx=t&15;
    size_t m0=(size_t)blockIdx.x*128;
    int bcol=blockIdx.y*128;
    const float* Abase=A;
    const float* Bbase=Bw;
    if(mode==3){
        size_t b=m0>>11;
        Abase=eigs+(b*4097+1)*128+(m0&2047)*128;
        Bbase=g_hspec+b*16384;
    }
    float acc[8][8]={};
    int am=t>>1, akq=(t&1)*8;
    int bk=t>>4, bn=(t&15)*8;
    for(int k0=0;k0<Kdim;k0+=16){
        const float* ap;
        if(mode==1) ap=(k0<128)?(g_h+(m0+am)*128+k0+akq):(g_hprop+(m0+am)*128+(k0-128)+akq);
        else if(mode==3) ap=Abase+(size_t)am*128+k0+akq;
        else ap=Abase+(m0+am)*128+k0+akq;
        float4 v0=*(const float4*)ap, v1=*(const float4*)(ap+4);
        float av[8]={v0.x,v0.y,v0.z,v0.w,v1.x,v1.y,v1.z,v1.w};
        if(mode==2){
            #pragma unroll
            for(int i=0;i<8;i++){ int kg=k0+akq+i; av[i]=siluf(g_affA[kg]*av[i]+g_affC[kg]); }
        }
        #pragma unroll
        for(int i=0;i<8;i++) As[(akq+i)*128+am]=av[i];
        const float* bp=Bbase+(size_t)(k0+bk)*ldb+bcol+bn;
        *(float4*)&Bs[bk*128+bn]  =*(const float4*)bp;
        *(float4*)&Bs[bk*128+bn+4]=*(const float4*)(bp+4);
        __syncthreads();
        #pragma unroll
        for(int kk=0;kk<16;kk++){
            float4 a0=*(const float4*)&As[kk*128+ty*8];
            float4 a1=*(const float4*)&As[kk*128+ty*8+4];
            float4 b0=*(const float4*)&Bs[kk*128+tx*8];
            float4 b1=*(const float4*)&Bs[kk*128+tx*8+4];
            float aa[8]={a0.x,a0.y,a0.z,a0.w,a1.x,a1.y,a1.z,a1.w};
            float bv[8]={b0.x,b0.y,b0.z,b0.w,b1.x,b1.y,b1.z,b1.w};
            #pragma unroll
            for(int ri=0;ri<8;ri++)
                #pragma unroll
                for(int ci=0;ci<8;ci++) acc[ri][ci]+=aa[ri]*bv[ci];
        }
        __syncthreads();
    }
    float bb[8];
    #pragma unroll
    for(int ci=0;ci<8;ci++) bb[ci]=bias?bias[bcol+tx*8+ci]:0.f;
    float ls[8]={}, lq[8]={};
    #pragma unroll
    for(int ri=0;ri<8;ri++){
        float v[8];
        #pragma unroll
        for(int ci=0;ci<8;ci++){ v[ci]=acc[ri][ci]+bb[ci]; ls[ci]+=v[ci]; lq[ci]+=v[ci]*v[ci]; }
        size_t row=m0+ty*8+ri;
        *(float4*)&Cout[row*(size_t)ldc+bcol+tx*8]  =make_float4(v[0],v[1],v[2],v[3]);
        *(float4*)&Cout[row*(size_t)ldc+bcol+tx*8+4]=make_float4(v[4],v[5],v[6],v[7]);
    }
    if(do_stats){
        __syncthreads();
        #pragma unroll
        for(int ci=0;ci<8;ci++) As[ty*128+tx*8+ci]=ls[ci];
        __syncthreads();
        if(t<128){ float s=0.f; for(int q=0;q<16;q++) s+=As[q*128+t]; atomicAdd(&g_stsum[bcol+t],s); }
        __syncthreads();
        #pragma unroll
        for(int ci=0;ci<8;ci++) As[ty*128+tx*8+ci]=lq[ci];
        __syncthreads();
        if(t<128){ float s=0.f; for(int q=0;q<16;q++) s+=As[q*128+t]; atomicAdd(&g_stsq[bcol+t],s); }
    }
}

// ---------------- msg activation + segment-sum scatter ----------------
__global__ __launch_bounds__(256) void k_msg(const int* __restrict__ nbr){
    int warp=threadIdx.x>>5, lane=threadIdx.x&31;
    size_t e=(size_t)blockIdx.x*8+warp;
    const float* h2=g_H2+e*256;
    int j=lane*4;
    float4 f=*(const float4*)(h2+j);
    float4 c=*(const float4*)(h2+128+j);
    float fr[4]={f.x,f.y,f.z,f.w}, cr[4]={c.x,c.y,c.z,c.w}, o[4];
    #pragma unroll
    for(int s=0;s<4;s++){
        int jj=j+s;
        float fv=g_affA[jj]*fr[s]+g_affC[jj];
        float cv=g_affA[128+jj]*cr[s]+g_affC[128+jj];
        float sg=1.f/(1.f+__expf(-fv));
        float sp=fmaxf(cv,0.f)+log1pf(__expf(-fabsf(cv)));
        o[s]=sg*sp;
    }
    float* dst=g_h+(size_t)nbr[e]*128+j;
    atomicAdd(dst+0,o[0]); atomicAdd(dst+1,o[1]);
    atomicAdd(dst+2,o[2]); atomicAdd(dst+3,o[3]);
}

// ---------------- h_spec: per-batch Einv^T @ hb, V chunked x4, atomic accumulate ----------------
__global__ __launch_bounds__(256) void k_spec(const float* __restrict__ eigs){
    __shared__ float As[16*128];
    __shared__ float Bs[16*128];
    int t=threadIdx.x, ty=t>>4, tx=t&15;
    int b=blockIdx.x>>2, c=blockIdx.x&3;
    int v0=c*512;
    const float* Abase=eigs+((size_t)b*4097+1+2048)*128;   // evecs_inv rows
    const float* Hbase=g_h+((size_t)b*2048)*128;
    int vr=t>>4, cq=(t&15)*8;
    float acc[8][8]={};
    for(int vt=0;vt<512;vt+=16){
        const float* ap=Abase+(size_t)(v0+vt+vr)*128+cq;
        *(float4*)&As[vr*128+cq]  =*(const float4*)ap;
        *(float4*)&As[vr*128+cq+4]=*(const float4*)(ap+4);
        const float* bp=Hbase+(size_t)(v0+vt+vr)*128+cq;
        *(float4*)&Bs[vr*128+cq]  =*(const float4*)bp;
        *(float4*)&Bs[vr*128+cq+4]=*(const float4*)(bp+4);
        __syncthreads();
        #pragma unroll
        for(int vv=0;vv<16;vv++){
            float4 a0=*(const float4*)&As[vv*128+ty*8];
            float4 a1=*(const float4*)&As[vv*128+ty*8+4];
            float4 b0=*(const float4*)&Bs[vv*128+tx*8];
            float4 b1=*(const float4*)&Bs[vv*128+tx*8+4];
            float aa[8]={a0.x,a0.y,a0.z,a0.w,a1.x,a1.y,a1.z,a1.w};
            float bv[8]={b0.x,b0.y,b0.z,b0.w,b1.x,b1.y,b1.z,b1.w};
            #pragma unroll
            for(int ri=0;ri<8;ri++)
                #pragma unroll
                for(int ci=0;ci<8;ci++) acc[ri][ci]+=aa[ri]*bv[ci];
        }
        __syncthreads();
    }
    float* dst=g_hspec+(size_t)b*16384;
    #pragma unroll
    for(int ri=0;ri<8;ri++)
        #pragma unroll
        for(int ci=0;ci<8;ci++)
            atomicAdd(&dst[(ty*8+ri)*128+tx*8+ci],acc[ri][ci]);
}

// ---------------- h_spec *= exp(-lam*t) ----------------
__global__ void k_coeff(const float* __restrict__ eigs, const float* __restrict__ pt){
    int i=blockIdx.x*blockDim.x+threadIdx.x;   // B*128*128
    int b=i>>14, k=(i>>7)&127, hcol=i&127;
    float lam=eigs[(size_t)b*4097*128+k];
    float tt=fmaxf(pt[hcol],1e-6f);
    g_hspec[i]*=__expf(-lam*tt);
}

// ---------------- h += affA*y2 + affC ----------------
__global__ void k_update(){
    size_t i=(size_t)blockIdx.x*blockDim.x+threadIdx.x;
    int j=(int)((i*4)&127);
    float4 y=((const float4*)g_y2)[i];
    float4 h=((float4*)g_h)[i];
    h.x+=g_affA[j+0]*y.x+g_affC[j+0];
    h.y+=g_affA[j+1]*y.y+g_affC[j+1];
    h.z+=g_affA[j+2]*y.z+g_affC[j+2];
    h.w+=g_affA[j+3]*y.w+g_affC[j+3];
    ((float4*)g_h)[i]=h;
}

// ---------------- final projection + mean over V ----------------
__global__ __launch_bounds__(256) void k_out(const float* __restrict__ wo2){
    __shared__ float part[8];
    int warp=threadIdx.x>>5, lane=threadIdx.x&31;
    size_t row=(size_t)blockIdx.x*8+warp;
    int j=lane*4;
    float4 y=*(const float4*)&g_y1[row*128+j];
    float4 w=*(const float4*)&wo2[j];
    float v=0.f;
    v+=siluf(g_affA[j+0]*y.x+g_affC[j+0])*w.x;
    v+=siluf(g_affA[j+1]*y.y+g_affC[j+1])*w.y;
    v+=siluf(g_affA[j+2]*y.z+g_affC[j+2])*w.z;
    v+=siluf(g_affA[j+3]*y.w+g_affC[j+3])*w.w;
    #pragma unroll
    for(int s=16;s>0;s>>=1) v+=__shfl_xor_sync(0xffffffffu,v,s);
    if(lane==0) part[warp]=v;
    __syncthreads();
    if(threadIdx.x==0){
        float s=0.f;
        #pragma unroll
        for(int q=0;q<8;q++) s+=part[q];
        atomicAdd(&g_outacc[blockIdx.x>>8],s);   // 256 blocks per batch
    }
}

__global__ void k_final(float* out, const float* __restrict__ bo2){
    int b=threadIdx.x;
    if(b<BB) out[b]=g_outacc[b]*(1.f/(float)VV)+bo2[0];
}

// ---------------- launch ----------------
extern "C" void kernel_launch(void* const* d_in, const int* in_sizes, int n_in,
                              void* d_out, int out_size){
    const float* chem =(const float*)d_in[0];
    const int*   nbr  =(const int*)  d_in[1];
    const float* eigs =(const float*)d_in[2];
    const float* w1   =(const float*)d_in[3];
    const float* b1   =(const float*)d_in[4];
    const float* g1   =(const float*)d_in[5];
    const float* be1  =(const float*)d_in[6];
    const float* w2   =(const float*)d_in[7];
    const float* b2   =(const float*)d_in[8];
    const float* g2   =(const float*)d_in[9];
    const float* be2  =(const float*)d_in[10];
    const float* prop =(const float*)d_in[11];
    const float* pw1  =(const float*)d_in[12];
    const float* pb1  =(const float*)d_in[13];
    const float* pg1  =(const float*)d_in[14];
    const float* pbe1 =(const float*)d_in[15];
    const float* pw2  =(const float*)d_in[16];
    const float* pb2  =(const float*)d_in[17];
    const float* pg2  =(const float*)d_in[18];
    const float* pbe2 =(const float*)d_in[19];
    const float* wo1  =(const float*)d_in[20];
    const float* bo1  =(const float*)d_in[21];
    const float* go1  =(const float*)d_in[22];
    const float* beo1 =(const float*)d_in[23];
    const float* wo2  =(const float*)d_in[24];
    const float* bo2  =(const float*)d_in[25];
    (void)in_sizes; (void)n_in; (void)out_size;

    // chem MLP over E rows
    k_zero_h<<<4096,1024>>>();
    k_zero_st<<<1,256>>>();
    k_gemm1<<<EE/128,256>>>(chem,w1,b1);
    k_fold<<<1,256>>>(128,1.f/(float)EE,g1,be1);
    k_zero_st<<<1,256>>>();
    k_mm<<<dim3(EE/128,2),256>>>(2,0,0,nullptr,w2,256,b2,256,128,1);   // H2 = siluBN1(Y1)@w2+b2
    k_fold<<<1,256>>>(256,1.f/(float)EE,g2,be2);
    k_msg<<<EE/8,256>>>(nbr);                                          // h = segment_sum(msg)

    // propagation layers
    for(int l=0;l<3;l++){
        k_zero_spec<<<256,1024>>>();
        k_spec<<<256,256>>>(eigs);
        k_coeff<<<4096,256>>>(eigs,prop+l*128);
        k_mm<<<dim3(NNODE/128,1),256>>>(3,1,1,eigs,nullptr,128,nullptr,128,128,0);  // h_prop
        k_zero_st<<<1,256>>>();
        k_mm<<<dim3(NNODE/128,1),256>>>(1,1,2,nullptr,pw1+(size_t)l*256*128,128,pb1+l*128,128,256,1); // y1
        k_fold<<<1,256>>>(128,1.f/(float)NNODE,pg1+l*128,pbe1+l*128);
        k_zero_st<<<1,256>>>();
        k_mm<<<dim3(NNODE/128,1),256>>>(2,2,3,nullptr,pw2+(size_t)l*128*128,128,pb2+l*128,128,128,1); // y2
        k_fold<<<1,256>>>(128,1.f/(float)NNODE,pg2+l*128,pbe2+l*128);
        k_update<<<16384,256>>>();                                     // h += BN(y2)
    }

    // output head
    k_zero_st<<<1,256>>>();
    k_mm<<<dim3(NNODE/128,1),256>>>(0,1,2,nullptr,wo1,128,bo1,128,128,1);  // y1 = h@wo1+bo1
    k_fold<<<1,256>>>(128,1.f/(float)NNODE,go1,beo1);
    k_out<<<NNODE/8,256>>>(wo2);
    k_final<<<1,64>>>((float*)d_out,bo2);
}